// round 3
// baseline (speedup 1.0000x reference)
#include <cuda_runtime.h>
#include <cuda_bf16.h>

// SoftAttention collapsed form: for each of 400 (B*N) batches, every output
// row equals sum_j softmax_j(hs[j] . w[H:2H]) * hs[j]  (hs = 64x32 tile).
//
// R3: 128 threads per batch (4 warps x 16 rows). Per-warp issue budget cut
// ~4x vs R2; cross-warp softmax/output combine via 3 small smem rounds.
//
// Warp w, lane l: g = l>>3 (row subgroup), c4 = (l&7)*4 (column base).
// Warp owns rows { 16w + 4i + g : i = 0..3 }.

#define T_DIM 64
#define H_DIM 32
#define BATCH_ELEMS (T_DIM * H_DIM)   // 2048

__global__ __launch_bounds__(128, 16)
void soft_attention_kernel(const float* __restrict__ x,
                           const float* __restrict__ w,
                           float* __restrict__ out) {
    __shared__ float s_max[4];
    __shared__ float s_sum[4];
    __shared__ float s_ov[4 * H_DIM];   // per-warp partial output vectors

    const int tid  = threadIdx.x;
    const int wid  = tid >> 5;
    const int lane = tid & 31;
    const int g    = lane >> 3;
    const int c4   = (lane & 7) * 4;
    const int b    = blockIdx.x;

    const float* xb = x + (size_t)b * BATCH_ELEMS;

    // w2 fragment (only w[H:2H] matters) — same 128B line for all warps
    const float4 wv = *reinterpret_cast<const float4*>(w + H_DIM + c4);

    // ---- load this warp's 4 row-chunks (independent LDG.128)
    float4 v[4];
#pragma unroll
    for (int i = 0; i < 4; i++)
        v[i] = *reinterpret_cast<const float4*>(xb + (16 * wid + 4 * i + g) * H_DIM + c4);

    // ---- row scores: partial dot + reduce within 8-lane column group
    float s[4];
#pragma unroll
    for (int i = 0; i < 4; i++) {
        float d = fmaf(v[i].x, wv.x,
                  fmaf(v[i].y, wv.y,
                  fmaf(v[i].z, wv.z, v[i].w * wv.w)));
        d += __shfl_xor_sync(0xffffffffu, d, 1);
        d += __shfl_xor_sync(0xffffffffu, d, 2);
        d += __shfl_xor_sync(0xffffffffu, d, 4);
        s[i] = d;   // score of row 16w+4i+g, replicated in its 8-lane group
    }

    // ---- warp max over its 16 rows (values distinct only across g -> xor 8,16)
    float wm = fmaxf(fmaxf(s[0], s[1]), fmaxf(s[2], s[3]));
    wm = fmaxf(wm, __shfl_xor_sync(0xffffffffu, wm, 8));
    wm = fmaxf(wm, __shfl_xor_sync(0xffffffffu, wm, 16));
    if (lane == 0) s_max[wid] = wm;
    __syncthreads();

    const float gmax = fmaxf(fmaxf(s_max[0], s_max[1]),
                             fmaxf(s_max[2], s_max[3]));

    // ---- exp + warp-local sum, and unscaled output partial
    float lsum = 0.f;
    float4 acc = make_float4(0.f, 0.f, 0.f, 0.f);
#pragma unroll
    for (int i = 0; i < 4; i++) {
        const float e = __expf(s[i] - gmax);
        lsum += e;
        acc.x = fmaf(e, v[i].x, acc.x);
        acc.y = fmaf(e, v[i].y, acc.y);
        acc.z = fmaf(e, v[i].z, acc.z);
        acc.w = fmaf(e, v[i].w, acc.w);
    }
    // lsum counted 8x (replicated within col group); ratios unaffected, but
    // keep it exact: reduce only across g, then it's sum over 16 rows.
    lsum += __shfl_xor_sync(0xffffffffu, lsum, 8);
    lsum += __shfl_xor_sync(0xffffffffu, lsum, 16);

    // reduce acc across row subgroups -> warp partial for columns c4..c4+3
#pragma unroll
    for (int o = 8; o <= 16; o <<= 1) {
        acc.x += __shfl_xor_sync(0xffffffffu, acc.x, o);
        acc.y += __shfl_xor_sync(0xffffffffu, acc.y, o);
        acc.z += __shfl_xor_sync(0xffffffffu, acc.z, o);
        acc.w += __shfl_xor_sync(0xffffffffu, acc.w, o);
    }

    if (lane == 0) s_sum[wid] = lsum;
    if (lane < 8)   // 8 lanes x float4 = the warp's full 32-col partial
        *reinterpret_cast<float4*>(s_ov + wid * H_DIM + c4) = acc;
    __syncthreads();

    const float inv = 1.f / (s_sum[0] + s_sum[1] + s_sum[2] + s_sum[3]);

    // ---- combine 4 warp partials for this lane's columns, scale once
    float4 o0 = *reinterpret_cast<const float4*>(s_ov + 0 * H_DIM + c4);
    float4 o1 = *reinterpret_cast<const float4*>(s_ov + 1 * H_DIM + c4);
    float4 o2 = *reinterpret_cast<const float4*>(s_ov + 2 * H_DIM + c4);
    float4 o3 = *reinterpret_cast<const float4*>(s_ov + 3 * H_DIM + c4);
    float4 ov;
    ov.x = (o0.x + o1.x + o2.x + o3.x) * inv;
    ov.y = (o0.y + o1.y + o2.y + o3.y) * inv;
    ov.z = (o0.z + o1.z + o2.z + o3.z) * inv;
    ov.w = (o0.w + o1.w + o2.w + o3.w) * inv;

    // ---- broadcast-write this warp's 16 rows (4 STG.128 per lane)
    float* ob = out + (size_t)b * BATCH_ELEMS;
#pragma unroll
    for (int i = 0; i < 4; i++)
        *reinterpret_cast<float4*>(ob + (16 * wid + 4 * i + g) * H_DIM + c4) = ov;
}

extern "C" void kernel_launch(void* const* d_in, const int* in_sizes, int n_in,
                              void* d_out, int out_size) {
    // metadata order: inputs, rel_rec_t, rel_send_t, soft_att_w, soft_att_b
    const float* x = (const float*)d_in[0];
    const float* w = (const float*)d_in[3];
    float* out = (float*)d_out;

    const int batches = 8 * 50;  // B * N = 400
    soft_attention_kernel<<<batches, 128>>>(x, w, out);
}

// round 4
// speedup vs baseline: 1.0048x; 1.0048x over previous
#include <cuda_runtime.h>
#include <cuda_bf16.h>

// SoftAttention collapsed form: for each of 400 (B*N) batches, every output
// row equals sum_j softmax_j(hs[j] . w[H:2H]) * hs[j]  (hs = 64x32 tile).
//
// R4: single-barrier flash-combine. 4 warps/batch; each warp publishes
// (warp_max, warp_expsum, warp_partial_out[32]) in ONE smem round; after one
// __syncthreads every warp forms the global max and rescales partials by
// exp(m_w - m_g). Numerically identical to two-pass softmax.

#define T_DIM 64
#define H_DIM 32
#define BATCH_ELEMS (T_DIM * H_DIM)   // 2048

__global__ __launch_bounds__(128, 16)
void soft_attention_kernel(const float* __restrict__ x,
                           const float* __restrict__ w,
                           float* __restrict__ out) {
    __shared__ float s_max[4];
    __shared__ float s_sum[4];
    __shared__ float s_ov[4 * H_DIM];   // per-warp partial output vectors

    const int tid  = threadIdx.x;
    const int wid  = tid >> 5;
    const int lane = tid & 31;
    const int g    = lane >> 3;        // row subgroup 0..3
    const int c4   = (lane & 7) * 4;   // column base
    const int b    = blockIdx.x;

    const float* xb = x + (size_t)b * BATCH_ELEMS;

    // w2 fragment (only w[H:2H] matters) — single 128B line, L2-resident
    const float4 wv = *reinterpret_cast<const float4*>(w + H_DIM + c4);

    // ---- load this warp's 16 rows: 4 independent LDG.128
    float4 v[4];
#pragma unroll
    for (int i = 0; i < 4; i++)
        v[i] = *reinterpret_cast<const float4*>(xb + (16 * wid + 4 * i + g) * H_DIM + c4);

    // ---- row scores: partial dot + reduce within 8-lane column group
    float s[4];
#pragma unroll
    for (int i = 0; i < 4; i++) {
        float d = fmaf(v[i].x, wv.x,
                  fmaf(v[i].y, wv.y,
                  fmaf(v[i].z, wv.z, v[i].w * wv.w)));
        d += __shfl_xor_sync(0xffffffffu, d, 1);
        d += __shfl_xor_sync(0xffffffffu, d, 2);
        d += __shfl_xor_sync(0xffffffffu, d, 4);
        s[i] = d;   // score of row 16w+4i+g, replicated in its 8-lane group
    }

    // ---- warp-local max over its 16 rows (distinct only across g -> xor 8,16)
    float wm = fmaxf(fmaxf(s[0], s[1]), fmaxf(s[2], s[3]));
    wm = fmaxf(wm, __shfl_xor_sync(0xffffffffu, wm, 8));
    wm = fmaxf(wm, __shfl_xor_sync(0xffffffffu, wm, 16));

    // ---- exp against WARP max + warp-local expsum + unscaled partial out
    float lsum = 0.f;
    float4 acc = make_float4(0.f, 0.f, 0.f, 0.f);
#pragma unroll
    for (int i = 0; i < 4; i++) {
        const float e = __expf(s[i] - wm);
        lsum += e;
        acc.x = fmaf(e, v[i].x, acc.x);
        acc.y = fmaf(e, v[i].y, acc.y);
        acc.z = fmaf(e, v[i].z, acc.z);
        acc.w = fmaf(e, v[i].w, acc.w);
    }
    // each row counted once per 8-lane group; reduce across g only
    lsum += __shfl_xor_sync(0xffffffffu, lsum, 8);
    lsum += __shfl_xor_sync(0xffffffffu, lsum, 16);
#pragma unroll
    for (int o = 8; o <= 16; o <<= 1) {
        acc.x += __shfl_xor_sync(0xffffffffu, acc.x, o);
        acc.y += __shfl_xor_sync(0xffffffffu, acc.y, o);
        acc.z += __shfl_xor_sync(0xffffffffu, acc.z, o);
        acc.w += __shfl_xor_sync(0xffffffffu, acc.w, o);
    }

    // ---- publish (m_w, lsum_w, acc_w) — single smem round, single barrier
    if (lane == 0) { s_max[wid] = wm; s_sum[wid] = lsum; }
    if (lane < 8)
        *reinterpret_cast<float4*>(s_ov + wid * H_DIM + c4) = acc;
    __syncthreads();

    // ---- flash combine: rescale each warp's partials by exp(m_w - m_g)
    const float m0 = s_max[0], m1 = s_max[1], m2 = s_max[2], m3 = s_max[3];
    const float mg = fmaxf(fmaxf(m0, m1), fmaxf(m2, m3));
    const float f0 = __expf(m0 - mg), f1 = __expf(m1 - mg);
    const float f2 = __expf(m2 - mg), f3 = __expf(m3 - mg);

    const float tot = fmaf(s_sum[0], f0, fmaf(s_sum[1], f1,
                      fmaf(s_sum[2], f2, s_sum[3] * f3)));
    const float inv = 1.f / tot;

    float4 o0 = *reinterpret_cast<const float4*>(s_ov + 0 * H_DIM + c4);
    float4 o1 = *reinterpret_cast<const float4*>(s_ov + 1 * H_DIM + c4);
    float4 o2 = *reinterpret_cast<const float4*>(s_ov + 2 * H_DIM + c4);
    float4 o3 = *reinterpret_cast<const float4*>(s_ov + 3 * H_DIM + c4);
    float4 ov;
    ov.x = fmaf(o0.x, f0, fmaf(o1.x, f1, fmaf(o2.x, f2, o3.x * f3))) * inv;
    ov.y = fmaf(o0.y, f0, fmaf(o1.y, f1, fmaf(o2.y, f2, o3.y * f3))) * inv;
    ov.z = fmaf(o0.z, f0, fmaf(o1.z, f1, fmaf(o2.z, f2, o3.z * f3))) * inv;
    ov.w = fmaf(o0.w, f0, fmaf(o1.w, f1, fmaf(o2.w, f2, o3.w * f3))) * inv;

    // ---- broadcast-write this warp's 16 rows (4 STG.128 per lane)
    float* ob = out + (size_t)b * BATCH_ELEMS;
#pragma unroll
    for (int i = 0; i < 4; i++)
        *reinterpret_cast<float4*>(ob + (16 * wid + 4 * i + g) * H_DIM + c4) = ov;
}

extern "C" void kernel_launch(void* const* d_in, const int* in_sizes, int n_in,
                              void* d_out, int out_size) {
    // metadata order: inputs, rel_rec_t, rel_send_t, soft_att_w, soft_att_b
    const float* x = (const float*)d_in[0];
    const float* w = (const float*)d_in[3];
    float* out = (float*)d_out;

    const int batches = 8 * 50;  // B * N = 400
    soft_attention_kernel<<<batches, 128>>>(x, w, out);
}